// round 16
// baseline (speedup 1.0000x reference)
#include <cuda_runtime.h>
#include <math.h>

#define NN 256
#define BATCH 4096
#define TROWS 520          // padded step rows (active t: 0..508)

// Scratch (no device allocations allowed)
__device__ float4 g_coef2[TROWS * 128];   // SoA: [t*128 + k*32 + lane], slot m=4*lane+k
__device__ float4 g_coefB[TROWS * 32];    // boundary: slot m=4*lane-1 (identity lane 0)
__device__ float g_Whi[NN * NN];          // W^T tf32 hi plane
__device__ float g_Wlo[NN * NN];          // W^T tf32 lo plane

__device__ __forceinline__ float tf32_rna(float x) {
    unsigned u;
    asm("cvt.rna.tf32.f32 %0, %1;" : "=r"(u) : "f"(x));
    return __uint_as_float(u);
}

// ---------------------------------------------------------------------------
// Kernel A: schedule-ordered coefficients, SoA + boundary plane (256-thr).
// ---------------------------------------------------------------------------
__global__ void coef2_kernel(const float* __restrict__ theta,
                             const float* __restrict__ phi) {
    const int tid = threadIdx.x;
    const int t = blockIdx.x * 2 + (tid >> 7);   // 0..519
    const int m = tid & 127;                     // slot
    const int p = 2 * m + (t & 1);
    const int pmaxs = min(t, 508 - t);
    float4 out = make_float4(1.f, 0.f, 0.f, 0.f);
    if (p <= pmaxs) {
        const int l = (t - p) >> 1;
        const int idx = l * 255 - ((l * (l - 1)) >> 1) + p;
        float s, c;  sincosf(theta[idx], &s, &c);
        float ei, er; sincosf(phi[idx], &ei, &er);
        out = make_float4(c, s * er, s * ei, 0.f);
    }
    g_coef2[t * 128 + (m & 3) * 32 + (m >> 2)] = out;
    if ((m & 3) == 3 && m < 127)
        g_coefB[t * 32 + ((m + 1) >> 2)] = out;
    if (m == 0)
        g_coefB[t * 32] = make_float4(1.f, 0.f, 0.f, 0.f);
}

// ---------------------------------------------------------------------------
// Kernel B: TWO columns per warp, rows 8L..8L+7 of both in lane L's registers.
// Both columns share the same coefficient ring (zero extra loads/regs); the
// second column's 48 FMAs/step fill the latency shadow of the first.
// 32 CTAs x 128 thr -> 1 warp/SMSP (measured optimum).
// ---------------------------------------------------------------------------
#define MZI(cf, x0, y0, x1, y1) do {                       \
    const float c_ = (cf).x, sr_ = (cf).y, si_ = (cf).z;   \
    const float nx0 = c_*(x0) - sr_*(x1) - si_*(y1);       \
    const float ny0 = c_*(y0) - sr_*(y1) + si_*(x1);       \
    const float nx1 = sr_*(x0) - si_*(y0) + c_*(x1);       \
    const float ny1 = sr_*(y0) + si_*(x0) + c_*(y1);       \
    (x0) = nx0; (y0) = ny0; (x1) = nx1; (y1) = ny1;        \
} while (0)

#define LOADP(dst, tt) do {                                            \
    const float4* p_ = &g_coef2[(tt) * 128 + lane];                    \
    dst[0] = __ldg(p_);       dst[1] = __ldg(p_ + 32);                 \
    dst[2] = __ldg(p_ + 64);  dst[3] = __ldg(p_ + 96);                 \
} while (0)
#define LOADB(bdst, tt) do { bdst = __ldg(&g_coefB[(tt) * 32 + lane]); } while (0)

#define STEP_EVEN(cf) do {                                             \
    MZI(cf[0], ur[0], ui[0], ur[1], ui[1]);                            \
    MZI(cf[0], vr[0], vi[0], vr[1], vi[1]);                            \
    MZI(cf[1], ur[2], ui[2], ur[3], ui[3]);                            \
    MZI(cf[1], vr[2], vi[2], vr[3], vi[3]);                            \
    MZI(cf[2], ur[4], ui[4], ur[5], ui[5]);                            \
    MZI(cf[2], vr[4], vi[4], vr[5], vi[5]);                            \
    MZI(cf[3], ur[6], ui[6], ur[7], ui[7]);                            \
    MZI(cf[3], vr[6], vi[6], vr[7], vi[7]);                            \
} while (0)

#define STEP_ODD(cf, bcf) do {                                         \
    /* all shfls first: pre-update row0/row7 of both columns */        \
    const float rxu = __shfl_down_sync(0xffffffffu, ur[0], 1);         \
    const float ryu = __shfl_down_sync(0xffffffffu, ui[0], 1);         \
    const float rxv = __shfl_down_sync(0xffffffffu, vr[0], 1);         \
    const float ryv = __shfl_down_sync(0xffffffffu, vi[0], 1);         \
    const float lxu = __shfl_up_sync(0xffffffffu, ur[7], 1);           \
    const float lyu = __shfl_up_sync(0xffffffffu, ui[7], 1);           \
    const float lxv = __shfl_up_sync(0xffffffffu, vr[7], 1);           \
    const float lyv = __shfl_up_sync(0xffffffffu, vi[7], 1);           \
    MZI(cf[0], ur[1], ui[1], ur[2], ui[2]);                            \
    MZI(cf[0], vr[1], vi[1], vr[2], vi[2]);                            \
    MZI(cf[1], ur[3], ui[3], ur[4], ui[4]);                            \
    MZI(cf[1], vr[3], vi[3], vr[4], vi[4]);                            \
    MZI(cf[2], ur[5], ui[5], ur[6], ui[6]);                            \
    MZI(cf[2], vr[5], vi[5], vr[6], vi[6]);                            \
    {   /* upper boundary: row7 is v0, next lane's row0 is v1 */       \
        const float c_ = cf[3].x, sr_ = cf[3].y, si_ = cf[3].z;        \
        const float nxu = c_*ur[7] - sr_*rxu - si_*ryu;                \
        const float nyu = c_*ui[7] - sr_*ryu + si_*rxu;                \
        ur[7] = nxu; ui[7] = nyu;                                      \
        const float nxv = c_*vr[7] - sr_*rxv - si_*ryv;                \
        const float nyv = c_*vi[7] - sr_*ryv + si_*rxv;                \
        vr[7] = nxv; vi[7] = nyv;                                      \
    }                                                                  \
    {   /* lower boundary: prev lane's row7 is v0, row0 is v1 */       \
        const float bc = bcf.x, bs = bcf.y, bt = bcf.z;                \
        const float nxu = bs*lxu - bt*lyu + bc*ur[0];                  \
        const float nyu = bs*lyu + bt*lxu + bc*ui[0];                  \
        ur[0] = nxu; ui[0] = nyu;                                      \
        const float nxv = bs*lxv - bt*lyv + bc*vr[0];                  \
        const float nyv = bs*lyv + bt*lxv + bc*vi[0];                  \
        vr[0] = nxv; vi[0] = nyv;                                      \
    }                                                                  \
} while (0)

__global__ __launch_bounds__(128, 1) void build_u_kernel(const float* __restrict__ phi_ext) {
    const int lane = threadIdx.x & 31;
    const int j0 = blockIdx.x * 8 + 2 * (threadIdx.x >> 5);   // two columns: j0, j0+1

    float ur[8], ui[8], vr[8], vi[8];
    #pragma unroll
    for (int k = 0; k < 8; ++k) {
        ur[k] = (8 * lane + k == j0) ? 1.f : 0.f;     ui[k] = 0.f;
        vr[k] = (8 * lane + k == j0 + 1) ? 1.f : 0.f; vi[k] = 0.f;
    }

    float4 e0[4], o0[4], e1[4], o1[4], e2[4], o2[4];
    float4 b0, b1, b2;
    LOADP(e0, 0); LOADP(o0, 1); LOADB(b0, 1);
    LOADP(e1, 2); LOADP(o1, 3); LOADB(b1, 3);
    LOADP(e2, 4); LOADP(o2, 5); LOADB(b2, 5);

    int t = 6;
    #pragma unroll 1
    for (int it = 0; it < 85; ++it) {     // 85*6 = 510 steps (0..509; 509 inert)
        STEP_EVEN(e0); STEP_ODD(o0, b0);
        LOADP(e0, t); LOADP(o0, t + 1); LOADB(b0, t + 1);
        STEP_EVEN(e1); STEP_ODD(o1, b1);
        LOADP(e1, t + 2); LOADP(o1, t + 3); LOADB(b1, t + 3);
        STEP_EVEN(e2); STEP_ODD(o2, b2);
        LOADP(e2, t + 4); LOADP(o2, t + 5); LOADB(b2, t + 5);
        t += 6;
    }

    // phase screen, real part, tf32 hi/lo split for both columns
    #pragma unroll
    for (int k = 0; k < 8; ++k) {
        const int r = 8 * lane + k;
        float sp, cp;
        sincosf(__ldg(&phi_ext[r]), &sp, &cp);
        const float wa = cp * ur[k] - sp * ui[k];
        const float ha = tf32_rna(wa);
        g_Whi[j0 * NN + r] = ha;
        g_Wlo[j0 * NN + r] = tf32_rna(wa - ha);
        const float wb = cp * vr[k] - sp * vi[k];
        const float hb = tf32_rna(wb);
        g_Whi[(j0 + 1) * NN + r] = hb;
        g_Wlo[(j0 + 1) * NN + r] = tf32_rna(wb - hb);
    }
}

// ---------------------------------------------------------------------------
// Kernel C: 3xTF32 tensor-core GEMM (R13, 81.9us-proven, verbatim).
// ---------------------------------------------------------------------------
#define GBM 64
#define GBN 64
#define GBK 16
#define SP  72

__device__ __forceinline__ void mma_tf32(float* d, const unsigned* a,
                                         unsigned b0, unsigned b1) {
    asm volatile(
        "mma.sync.aligned.m16n8k8.row.col.f32.tf32.tf32.f32 "
        "{%0,%1,%2,%3}, {%4,%5,%6,%7}, {%8,%9}, {%0,%1,%2,%3};"
        : "+f"(d[0]), "+f"(d[1]), "+f"(d[2]), "+f"(d[3])
        : "r"(a[0]), "r"(a[1]), "r"(a[2]), "r"(a[3]), "r"(b0), "r"(b1));
}

__global__ __launch_bounds__(128, 4) void gemm_tc_kernel(const float* __restrict__ A,
                                                         float* __restrict__ C) {
    __shared__ float Ah[GBK][SP], Al[GBK][SP], Bh[GBK][SP], Bl[GBK][SP];

    const int tid  = threadIdx.x;
    const int wid  = tid >> 5;
    const int lane = tid & 31;
    const int g    = lane >> 2;
    const int th   = lane & 3;
    const int wm0  = (wid & 1) * 32;
    const int wn0  = (wid >> 1) * 32;
    const int bm0  = blockIdx.x * GBM;
    const int bn0  = blockIdx.y * GBN;

    const int am  = tid >> 1;
    const int akc = (tid & 1) * 8;
    const int bk  = tid >> 3;
    const int bnc = (tid & 7) * 8;

    float acc[2][4][4];
    #pragma unroll
    for (int mt = 0; mt < 2; ++mt)
        #pragma unroll
        for (int nt = 0; nt < 4; ++nt)
            #pragma unroll
            for (int q = 0; q < 4; ++q) acc[mt][nt][q] = 0.f;

    float4 pa0, pa1, pbh0, pbh1, pbl0, pbl1;
    {
        const float* ap = A + (bm0 + am) * NN + akc;
        pa0 = *reinterpret_cast<const float4*>(ap);
        pa1 = *reinterpret_cast<const float4*>(ap + 4);
        const float* bp  = g_Whi + bk * NN + bn0 + bnc;
        const float* cp2 = g_Wlo + bk * NN + bn0 + bnc;
        pbh0 = *reinterpret_cast<const float4*>(bp);
        pbh1 = *reinterpret_cast<const float4*>(bp + 4);
        pbl0 = *reinterpret_cast<const float4*>(cp2);
        pbl1 = *reinterpret_cast<const float4*>(cp2 + 4);
    }

    #pragma unroll 1
    for (int it = 0; it < NN / GBK; ++it) {
        {
            float av[8] = {pa0.x, pa0.y, pa0.z, pa0.w, pa1.x, pa1.y, pa1.z, pa1.w};
            #pragma unroll
            for (int u = 0; u < 8; ++u) {
                const float hi = tf32_rna(av[u]);
                Ah[akc + u][am] = hi;
                Al[akc + u][am] = tf32_rna(av[u] - hi);
            }
            *reinterpret_cast<float4*>(&Bh[bk][bnc])     = pbh0;
            *reinterpret_cast<float4*>(&Bh[bk][bnc + 4]) = pbh1;
            *reinterpret_cast<float4*>(&Bl[bk][bnc])     = pbl0;
            *reinterpret_cast<float4*>(&Bl[bk][bnc + 4]) = pbl1;
        }
        __syncthreads();

        if (it + 1 < NN / GBK) {
            const int k0 = (it + 1) * GBK;
            const float* ap = A + (bm0 + am) * NN + k0 + akc;
            pa0 = *reinterpret_cast<const float4*>(ap);
            pa1 = *reinterpret_cast<const float4*>(ap + 4);
            const float* bp  = g_Whi + (k0 + bk) * NN + bn0 + bnc;
            const float* cp2 = g_Wlo + (k0 + bk) * NN + bn0 + bnc;
            pbh0 = *reinterpret_cast<const float4*>(bp);
            pbh1 = *reinterpret_cast<const float4*>(bp + 4);
            pbl0 = *reinterpret_cast<const float4*>(cp2);
            pbl1 = *reinterpret_cast<const float4*>(cp2 + 4);
        }

        #pragma unroll
        for (int ks = 0; ks < GBK; ks += 8) {
            unsigned ah[2][4], al[2][4];
            #pragma unroll
            for (int mt = 0; mt < 2; ++mt) {
                const int mb = wm0 + mt * 16 + g;
                ah[mt][0] = __float_as_uint(Ah[ks + th][mb]);
                ah[mt][1] = __float_as_uint(Ah[ks + th][mb + 8]);
                ah[mt][2] = __float_as_uint(Ah[ks + th + 4][mb]);
                ah[mt][3] = __float_as_uint(Ah[ks + th + 4][mb + 8]);
                al[mt][0] = __float_as_uint(Al[ks + th][mb]);
                al[mt][1] = __float_as_uint(Al[ks + th][mb + 8]);
                al[mt][2] = __float_as_uint(Al[ks + th + 4][mb]);
                al[mt][3] = __float_as_uint(Al[ks + th + 4][mb + 8]);
            }
            #pragma unroll
            for (int nt = 0; nt < 4; ++nt) {
                const int nb = wn0 + nt * 8 + g;
                const unsigned bh0 = __float_as_uint(Bh[ks + th][nb]);
                const unsigned bh1 = __float_as_uint(Bh[ks + th + 4][nb]);
                const unsigned bl0 = __float_as_uint(Bl[ks + th][nb]);
                const unsigned bl1 = __float_as_uint(Bl[ks + th + 4][nb]);
                #pragma unroll
                for (int mt = 0; mt < 2; ++mt) {
                    mma_tf32(acc[mt][nt], ah[mt], bh0, bh1);
                    mma_tf32(acc[mt][nt], ah[mt], bl0, bl1);
                    mma_tf32(acc[mt][nt], al[mt], bh0, bh1);
                }
            }
        }
        __syncthreads();
    }

    #pragma unroll
    for (int mt = 0; mt < 2; ++mt) {
        #pragma unroll
        for (int nt = 0; nt < 4; ++nt) {
            const int row = bm0 + wm0 + mt * 16 + g;
            const int col = bn0 + wn0 + nt * 8 + 2 * th;
            *reinterpret_cast<float2*>(C + row * NN + col) =
                make_float2(acc[mt][nt][0], acc[mt][nt][1]);
            *reinterpret_cast<float2*>(C + (row + 8) * NN + col) =
                make_float2(acc[mt][nt][2], acc[mt][nt][3]);
        }
    }
}

// ---------------------------------------------------------------------------
// Launch: inputs (metadata order): x, theta, phi_internal, phi_external
// ---------------------------------------------------------------------------
extern "C" void kernel_launch(void* const* d_in, const int* in_sizes, int n_in,
                              void* d_out, int out_size) {
    const float* x       = (const float*)d_in[0];
    const float* theta   = (const float*)d_in[1];
    const float* phi_int = (const float*)d_in[2];
    const float* phi_ext = (const float*)d_in[3];
    float* out = (float*)d_out;

    coef2_kernel<<<TROWS / 2, 256>>>(theta, phi_int);
    build_u_kernel<<<NN / 8, 128>>>(phi_ext);
    gemm_tc_kernel<<<dim3(BATCH / GBM, NN / GBN), 128>>>(x, out);
}

// round 17
// speedup vs baseline: 1.2559x; 1.2559x over previous
#include <cuda_runtime.h>
#include <math.h>

#define NN 256
#define BATCH 4096
#define TROWS 520          // padded step rows (active t: 0..508)

// Scratch (no device allocations allowed)
__device__ float4 g_coef2[TROWS * 128];   // full layout SoA
__device__ float4 g_coefB[TROWS * 32];    // full boundary plane
__device__ float4 g_coefH[TROWS * 64];    // half layout SoA
__device__ float4 g_coefHB[TROWS * 32];   // half boundary plane
__device__ float g_Whi[NN * NN];          // W^T tf32 hi plane
__device__ float g_Wlo[NN * NN];          // W^T tf32 lo plane

__device__ __forceinline__ float tf32_rna(float x) {
    unsigned u;
    asm("cvt.rna.tf32.f32 %0, %1;" : "=r"(u) : "f"(x));
    return __uint_as_float(u);
}

// ---------------------------------------------------------------------------
// Kernel A: schedule-ordered coefficients (identity padding), fast sincos.
// ---------------------------------------------------------------------------
__global__ void coef2_kernel(const float* __restrict__ theta,
                             const float* __restrict__ phi) {
    const int tid = threadIdx.x;
    const int t = blockIdx.x * 2 + (tid >> 7);   // 0..519
    const int m = tid & 127;                     // slot
    const int p = 2 * m + (t & 1);
    const int pmaxs = min(t, 508 - t);
    float4 out = make_float4(1.f, 0.f, 0.f, 0.f);
    if (p <= pmaxs) {
        const int l = (t - p) >> 1;
        const int idx = l * 255 - ((l * (l - 1)) >> 1) + p;
        float s, c;  __sincosf(theta[idx], &s, &c);
        float ei, er; __sincosf(phi[idx], &ei, &er);
        out = make_float4(c, s * er, s * ei, 0.f);
    }
    g_coef2[t * 128 + (m & 3) * 32 + (m >> 2)] = out;
    if ((m & 3) == 3 && m < 127)
        g_coefB[t * 32 + ((m + 1) >> 2)] = out;
    if (m == 0)
        g_coefB[t * 32] = make_float4(1.f, 0.f, 0.f, 0.f);
    if (m < 64)
        g_coefH[t * 64 + (m & 1) * 32 + (m >> 1)] = out;
    if ((m & 1) == 1 && m <= 61)
        g_coefHB[t * 32 + ((m + 1) >> 1)] = out;
    if (m == 0)
        g_coefHB[t * 32] = make_float4(1.f, 0.f, 0.f, 0.f);
}

// ---------------------------------------------------------------------------
// Kernel B: warp-per-column systolic build, wavefront-phased layouts
// (R13-proven, verbatim). Epilogues emit tf32 hi/lo planes of W^T.
// ---------------------------------------------------------------------------
#define MZI(cf, x0, y0, x1, y1) do {                       \
    const float c_ = (cf).x, sr_ = (cf).y, si_ = (cf).z;   \
    const float nx0 = c_*(x0) - sr_*(x1) - si_*(y1);       \
    const float ny0 = c_*(y0) - sr_*(y1) + si_*(x1);       \
    const float nx1 = sr_*(x0) - si_*(y0) + c_*(x1);       \
    const float ny1 = sr_*(y0) + si_*(x0) + c_*(y1);       \
    (x0) = nx0; (y0) = ny0; (x1) = nx1; (y1) = ny1;        \
} while (0)

#define LOADP(dst, tt) do {                                            \
    const float4* p_ = &g_coef2[(tt) * 128 + lane];                    \
    dst[0] = __ldg(p_);       dst[1] = __ldg(p_ + 32);                 \
    dst[2] = __ldg(p_ + 64);  dst[3] = __ldg(p_ + 96);                 \
} while (0)
#define LOADB(bdst, tt)  do { bdst = __ldg(&g_coefB[(tt) * 32 + lane]); } while (0)
#define LOADH(dst, tt) do {                                            \
    const float4* p_ = &g_coefH[(tt) * 64 + lane];                     \
    dst[0] = __ldg(p_); dst[1] = __ldg(p_ + 32);                       \
} while (0)
#define LOADHB(bdst, tt) do { bdst = __ldg(&g_coefHB[(tt) * 32 + lane]); } while (0)

#define STEP_EVEN(cf) do {                                             \
    MZI(cf[0], vr[0], vi[0], vr[1], vi[1]);                            \
    MZI(cf[1], vr[2], vi[2], vr[3], vi[3]);                            \
    MZI(cf[2], vr[4], vi[4], vr[5], vi[5]);                            \
    MZI(cf[3], vr[6], vi[6], vr[7], vi[7]);                            \
} while (0)

#define STEP_ODD(cf, bcf) do {                                         \
    const float rx = __shfl_down_sync(0xffffffffu, vr[0], 1);          \
    const float ry = __shfl_down_sync(0xffffffffu, vi[0], 1);          \
    const float lx = __shfl_up_sync(0xffffffffu, vr[7], 1);            \
    const float ly = __shfl_up_sync(0xffffffffu, vi[7], 1);            \
    MZI(cf[0], vr[1], vi[1], vr[2], vi[2]);                            \
    MZI(cf[1], vr[3], vi[3], vr[4], vi[4]);                            \
    MZI(cf[2], vr[5], vi[5], vr[6], vi[6]);                            \
    {                                                                  \
        const float c_ = cf[3].x, sr_ = cf[3].y, si_ = cf[3].z;        \
        const float nx = c_*vr[7] - sr_*rx - si_*ry;                   \
        const float ny = c_*vi[7] - sr_*ry + si_*rx;                   \
        vr[7] = nx; vi[7] = ny;                                        \
    }                                                                  \
    {                                                                  \
        const float bc = bcf.x, bs = bcf.y, bt = bcf.z;                \
        const float nx = bs*lx - bt*ly + bc*vr[0];                     \
        const float ny = bs*ly + bt*lx + bc*vi[0];                     \
        vr[0] = nx; vi[0] = ny;                                        \
    }                                                                  \
} while (0)

#define HSTEP_EVEN(cf) do {                                            \
    MZI(cf[0], vr[0], vi[0], vr[1], vi[1]);                            \
    MZI(cf[1], vr[2], vi[2], vr[3], vi[3]);                            \
} while (0)

#define HSTEP_ODD(cf, bcf) do {                                        \
    const float rx = __shfl_down_sync(0xffffffffu, vr[0], 1);          \
    const float ry = __shfl_down_sync(0xffffffffu, vi[0], 1);          \
    const float lx = __shfl_up_sync(0xffffffffu, vr[3], 1);            \
    const float ly = __shfl_up_sync(0xffffffffu, vi[3], 1);            \
    MZI(cf[0], vr[1], vi[1], vr[2], vi[2]);                            \
    {                                                                  \
        const float c_ = cf[1].x, sr_ = cf[1].y, si_ = cf[1].z;        \
        const float nx = c_*vr[3] - sr_*rx - si_*ry;                   \
        const float ny = c_*vi[3] - sr_*ry + si_*rx;                   \
        vr[3] = nx; vi[3] = ny;                                        \
    }                                                                  \
    {                                                                  \
        const float bc = bcf.x, bs = bcf.y, bt = bcf.z;                \
        const float nx = bs*lx - bt*ly + bc*vr[0];                     \
        const float ny = bs*ly + bt*lx + bc*vi[0];                     \
        vr[0] = nx; vi[0] = ny;                                        \
    }                                                                  \
} while (0)

__global__ __launch_bounds__(128, 1) void build_u_kernel(const float* __restrict__ phi_ext) {
    const int lane = threadIdx.x & 31;
    const int j = blockIdx.x * 4 + (threadIdx.x >> 5);

    float vr[8], vi[8];

    // phase 1: half layout, t = 0..125
    #pragma unroll
    for (int k = 0; k < 4; ++k) {
        vr[k] = (4 * lane + k == j) ? 1.f : 0.f;
        vi[k] = 0.f;
    }
    {
        float4 e0[2], o0[2], e1[2], o1[2], e2[2], o2[2];
        float4 b0, b1, b2;
        LOADH(e0, 0); LOADH(o0, 1); LOADHB(b0, 1);
        LOADH(e1, 2); LOADH(o1, 3); LOADHB(b1, 3);
        LOADH(e2, 4); LOADH(o2, 5); LOADHB(b2, 5);
        int t = 6;
        #pragma unroll 1
        for (int it = 0; it < 21; ++it) {
            HSTEP_EVEN(e0); HSTEP_ODD(o0, b0);
            LOADH(e0, t); LOADH(o0, t + 1); LOADHB(b0, t + 1);
            HSTEP_EVEN(e1); HSTEP_ODD(o1, b1);
            LOADH(e1, t + 2); LOADH(o1, t + 3); LOADHB(b1, t + 3);
            HSTEP_EVEN(e2); HSTEP_ODD(o2, b2);
            LOADH(e2, t + 4); LOADH(o2, t + 5); LOADHB(b2, t + 5);
            t += 6;
        }
    }

    // transition half -> full
    {
        float nr[8], ni[8];
        #pragma unroll
        for (int k = 0; k < 4; ++k) {
            const float ra = __shfl_sync(0xffffffffu, vr[k], 2 * lane);
            const float rb = __shfl_sync(0xffffffffu, vr[k], 2 * lane + 1);
            const float ia = __shfl_sync(0xffffffffu, vi[k], 2 * lane);
            const float ib = __shfl_sync(0xffffffffu, vi[k], 2 * lane + 1);
            if (lane < 16) {
                nr[k] = ra;     ni[k] = ia;
                nr[k + 4] = rb; ni[k + 4] = ib;
            } else {
                nr[k]     = (8 * lane + k == j)     ? 1.f : 0.f; ni[k] = 0.f;
                nr[k + 4] = (8 * lane + k + 4 == j) ? 1.f : 0.f; ni[k + 4] = 0.f;
            }
        }
        #pragma unroll
        for (int k = 0; k < 8; ++k) { vr[k] = nr[k]; vi[k] = ni[k]; }
    }

    // phase 2: full layout, t = 126..383
    {
        float4 e0[4], o0[4], e1[4], o1[4], e2[4], o2[4];
        float4 b0, b1, b2;
        LOADP(e0, 126); LOADP(o0, 127); LOADB(b0, 127);
        LOADP(e1, 128); LOADP(o1, 129); LOADB(b1, 129);
        LOADP(e2, 130); LOADP(o2, 131); LOADB(b2, 131);
        int t = 132;
        #pragma unroll 1
        for (int it = 0; it < 43; ++it) {
            STEP_EVEN(e0); STEP_ODD(o0, b0);
            LOADP(e0, t); LOADP(o0, t + 1); LOADB(b0, t + 1);
            STEP_EVEN(e1); STEP_ODD(o1, b1);
            LOADP(e1, t + 2); LOADP(o1, t + 3); LOADB(b1, t + 3);
            STEP_EVEN(e2); STEP_ODD(o2, b2);
            LOADP(e2, t + 4); LOADP(o2, t + 5); LOADB(b2, t + 5);
            t += 6;
        }
    }

    // transition full -> half: rows 128..255 final -> store hi/lo planes
    if (lane >= 16) {
        #pragma unroll
        for (int k = 0; k < 8; ++k) {
            const int r = 8 * lane + k;
            float sp, cp;
            sincosf(__ldg(&phi_ext[r]), &sp, &cp);
            const float w = cp * vr[k] - sp * vi[k];
            const float hi = tf32_rna(w);
            g_Whi[j * NN + r] = hi;
            g_Wlo[j * NN + r] = tf32_rna(w - hi);
        }
    }
    {
        float nr[4], ni[4];
        #pragma unroll
        for (int k = 0; k < 4; ++k) {
            const float ra = __shfl_sync(0xffffffffu, vr[k],     lane >> 1);
            const float rb = __shfl_sync(0xffffffffu, vr[k + 4], lane >> 1);
            const float ia = __shfl_sync(0xffffffffu, vi[k],     lane >> 1);
            const float ib = __shfl_sync(0xffffffffu, vi[k + 4], lane >> 1);
            nr[k] = (lane & 1) ? rb : ra;
            ni[k] = (lane & 1) ? ib : ia;
        }
        #pragma unroll
        for (int k = 0; k < 4; ++k) { vr[k] = nr[k]; vi[k] = ni[k]; }
    }

    // phase 3: half layout, t = 384..509
    {
        float4 e0[2], o0[2], e1[2], o1[2], e2[2], o2[2];
        float4 b0, b1, b2;
        LOADH(e0, 384); LOADH(o0, 385); LOADHB(b0, 385);
        LOADH(e1, 386); LOADH(o1, 387); LOADHB(b1, 387);
        LOADH(e2, 388); LOADH(o2, 389); LOADHB(b2, 389);
        int t = 390;
        #pragma unroll 1
        for (int it = 0; it < 21; ++it) {
            HSTEP_EVEN(e0); HSTEP_ODD(o0, b0);
            LOADH(e0, t); LOADH(o0, t + 1); LOADHB(b0, t + 1);
            HSTEP_EVEN(e1); HSTEP_ODD(o1, b1);
            LOADH(e1, t + 2); LOADH(o1, t + 3); LOADHB(b1, t + 3);
            HSTEP_EVEN(e2); HSTEP_ODD(o2, b2);
            LOADH(e2, t + 4); LOADH(o2, t + 5); LOADHB(b2, t + 5);
            t += 6;
        }
    }

    // final store: rows 0..127 -> hi/lo planes
    #pragma unroll
    for (int k = 0; k < 4; ++k) {
        const int r = 4 * lane + k;
        float sp, cp;
        sincosf(__ldg(&phi_ext[r]), &sp, &cp);
        const float w = cp * vr[k] - sp * vi[k];
        const float hi = tf32_rna(w);
        g_Whi[j * NN + r] = hi;
        g_Wlo[j * NN + r] = tf32_rna(w - hi);
    }
}

// ---------------------------------------------------------------------------
// Kernel C: 3xTF32 tensor-core GEMM, double-buffered smem (ONE sync/iter).
// CTA tile 64x64, 128 thr, grid 64x4; SP=72 conflict-free fragment LDS.
// D += Ah*Bh + Ah*Bl + Al*Bh.
// ---------------------------------------------------------------------------
#define GBM 64
#define GBN 64
#define GBK 16
#define SP  72

__device__ __forceinline__ void mma_tf32(float* d, const unsigned* a,
                                         unsigned b0, unsigned b1) {
    asm volatile(
        "mma.sync.aligned.m16n8k8.row.col.f32.tf32.tf32.f32 "
        "{%0,%1,%2,%3}, {%4,%5,%6,%7}, {%8,%9}, {%0,%1,%2,%3};"
        : "+f"(d[0]), "+f"(d[1]), "+f"(d[2]), "+f"(d[3])
        : "r"(a[0]), "r"(a[1]), "r"(a[2]), "r"(a[3]), "r"(b0), "r"(b1));
}

__global__ __launch_bounds__(128, 4) void gemm_tc_kernel(const float* __restrict__ A,
                                                         float* __restrict__ C) {
    __shared__ float Ah[2][GBK][SP], Al[2][GBK][SP], Bh[2][GBK][SP], Bl[2][GBK][SP];

    const int tid  = threadIdx.x;
    const int wid  = tid >> 5;
    const int lane = tid & 31;
    const int g    = lane >> 2;
    const int th   = lane & 3;
    const int wm0  = (wid & 1) * 32;
    const int wn0  = (wid >> 1) * 32;
    const int bm0  = blockIdx.x * GBM;
    const int bn0  = blockIdx.y * GBN;

    const int am  = tid >> 1;
    const int akc = (tid & 1) * 8;
    const int bk  = tid >> 3;
    const int bnc = (tid & 7) * 8;

    float acc[2][4][4];
    #pragma unroll
    for (int mt = 0; mt < 2; ++mt)
        #pragma unroll
        for (int nt = 0; nt < 4; ++nt)
            #pragma unroll
            for (int q = 0; q < 4; ++q) acc[mt][nt][q] = 0.f;

    float4 pa0, pa1, pbh0, pbh1, pbl0, pbl1;
    {
        const float* ap = A + (bm0 + am) * NN + akc;
        pa0 = *reinterpret_cast<const float4*>(ap);
        pa1 = *reinterpret_cast<const float4*>(ap + 4);
        const float* bp  = g_Whi + bk * NN + bn0 + bnc;
        const float* cp2 = g_Wlo + bk * NN + bn0 + bnc;
        pbh0 = *reinterpret_cast<const float4*>(bp);
        pbh1 = *reinterpret_cast<const float4*>(bp + 4);
        pbl0 = *reinterpret_cast<const float4*>(cp2);
        pbl1 = *reinterpret_cast<const float4*>(cp2 + 4);
    }

    #pragma unroll 1
    for (int it = 0; it < NN / GBK; ++it) {
        const int buf = it & 1;
        // stage prefetched data into buf
        {
            float av[8] = {pa0.x, pa0.y, pa0.z, pa0.w, pa1.x, pa1.y, pa1.z, pa1.w};
            #pragma unroll
            for (int u = 0; u < 8; ++u) {
                const float hi = tf32_rna(av[u]);
                Ah[buf][akc + u][am] = hi;
                Al[buf][akc + u][am] = tf32_rna(av[u] - hi);
            }
            *reinterpret_cast<float4*>(&Bh[buf][bk][bnc])     = pbh0;
            *reinterpret_cast<float4*>(&Bh[buf][bk][bnc + 4]) = pbh1;
            *reinterpret_cast<float4*>(&Bl[buf][bk][bnc])     = pbl0;
            *reinterpret_cast<float4*>(&Bl[buf][bk][bnc + 4]) = pbl1;
        }
        __syncthreads();   // single sync per iteration (double-buffered)

        if (it + 1 < NN / GBK) {
            const int k0 = (it + 1) * GBK;
            const float* ap = A + (bm0 + am) * NN + k0 + akc;
            pa0 = *reinterpret_cast<const float4*>(ap);
            pa1 = *reinterpret_cast<const float4*>(ap + 4);
            const float* bp  = g_Whi + (k0 + bk) * NN + bn0 + bnc;
            const float* cp2 = g_Wlo + (k0 + bk) * NN + bn0 + bnc;
            pbh0 = *reinterpret_cast<const float4*>(bp);
            pbh1 = *reinterpret_cast<const float4*>(bp + 4);
            pbl0 = *reinterpret_cast<const float4*>(cp2);
            pbl1 = *reinterpret_cast<const float4*>(cp2 + 4);
        }

        #pragma unroll
        for (int ks = 0; ks < GBK; ks += 8) {
            unsigned ah[2][4], al[2][4];
            #pragma unroll
            for (int mt = 0; mt < 2; ++mt) {
                const int mb = wm0 + mt * 16 + g;
                ah[mt][0] = __float_as_uint(Ah[buf][ks + th][mb]);
                ah[mt][1] = __float_as_uint(Ah[buf][ks + th][mb + 8]);
                ah[mt][2] = __float_as_uint(Ah[buf][ks + th + 4][mb]);
                ah[mt][3] = __float_as_uint(Ah[buf][ks + th + 4][mb + 8]);
                al[mt][0] = __float_as_uint(Al[buf][ks + th][mb]);
                al[mt][1] = __float_as_uint(Al[buf][ks + th][mb + 8]);
                al[mt][2] = __float_as_uint(Al[buf][ks + th + 4][mb]);
                al[mt][3] = __float_as_uint(Al[buf][ks + th + 4][mb + 8]);
            }
            #pragma unroll
            for (int nt = 0; nt < 4; ++nt) {
                const int nb = wn0 + nt * 8 + g;
                const unsigned bh0 = __float_as_uint(Bh[buf][ks + th][nb]);
                const unsigned bh1 = __float_as_uint(Bh[buf][ks + th + 4][nb]);
                const unsigned bl0 = __float_as_uint(Bl[buf][ks + th][nb]);
                const unsigned bl1 = __float_as_uint(Bl[buf][ks + th + 4][nb]);
                #pragma unroll
                for (int mt = 0; mt < 2; ++mt) {
                    mma_tf32(acc[mt][nt], ah[mt], bh0, bh1);
                    mma_tf32(acc[mt][nt], ah[mt], bl0, bl1);
                    mma_tf32(acc[mt][nt], al[mt], bh0, bh1);
                }
            }
        }
    }

    #pragma unroll
    for (int mt = 0; mt < 2; ++mt) {
        #pragma unroll
        for (int nt = 0; nt < 4; ++nt) {
            const int row = bm0 + wm0 + mt * 16 + g;
            const int col = bn0 + wn0 + nt * 8 + 2 * th;
            *reinterpret_cast<float2*>(C + row * NN + col) =
                make_float2(acc[mt][nt][0], acc[mt][nt][1]);
            *reinterpret_cast<float2*>(C + (row + 8) * NN + col) =
                make_float2(acc[mt][nt][2], acc[mt][nt][3]);
        }
    }
}

// ---------------------------------------------------------------------------
// Launch: inputs (metadata order): x, theta, phi_internal, phi_external
// ---------------------------------------------------------------------------
extern "C" void kernel_launch(void* const* d_in, const int* in_sizes, int n_in,
                              void* d_out, int out_size) {
    const float* x       = (const float*)d_in[0];
    const float* theta   = (const float*)d_in[1];
    const float* phi_int = (const float*)d_in[2];
    const float* phi_ext = (const float*)d_in[3];
    float* out = (float*)d_out;

    coef2_kernel<<<TROWS / 2, 256>>>(theta, phi_int);
    build_u_kernel<<<NN / 4, 128>>>(phi_ext);
    gemm_tc_kernel<<<dim3(BATCH / GBM, NN / GBN), 128>>>(x, out);
}